// round 5
// baseline (speedup 1.0000x reference)
#include <cuda_runtime.h>
#include <cuda_bf16.h>
#include <math.h>
#include <stdint.h>

// ---------------- problem constants ----------------
#define NLAYERS 6
#define Bb      4
#define Ls      1024
#define DM      512
#define DI      1024
#define NH      16
#define HD      64
#define NS      16
#define CONV_DIM 1056
#define DPROJ   2096
#define DPROJ_PAD 2176          // 17 * 128
#define DFF     2048
#define RWS     4096            // B*L rows
#define EPSF    1e-5f

// per-layer packed weight offsets (padded, elements)
#define LW_IN   (DPROJ_PAD * DM)
#define LW_OUT  (DM * DI)
#define LW_F1   (DFF * DM)
#define LW_F2   (DM * DFF)
#define LW_TOT  (LW_IN + LW_OUT + LW_F1 + LW_F2)

// ---------------- scratch (device globals) ----------------
__device__ float g_x  [RWS * DM];
__device__ float g_zx [RWS * DPROJ];
__device__ float g_xbc[RWS * CONV_DIM];
__device__ float g_dt [RWS * NH];
__device__ float g_dA [RWS * NH];
__device__ float g_y  [RWS * DI];
__device__ __nv_bfloat16 g_xnh[RWS * DM],  g_xnl[RWS * DM];
__device__ __nv_bfloat16 g_ygh[RWS * DI],  g_ygl[RWS * DI];
__device__ __nv_bfloat16 g_fh [RWS * DFF], g_fl [RWS * DFF];
__device__ __nv_bfloat16 g_wh [NLAYERS * LW_TOT], g_wl[NLAYERS * LW_TOT];

// ---------------- small helpers ----------------
__device__ __forceinline__ float gelu_exact(float v) {
    return 0.5f * v * (1.0f + erff(v * 0.70710678118654752f));
}
__device__ __forceinline__ float silu_f(float v) {
    return v / (1.0f + expf(-v));
}
__device__ __forceinline__ void split_bf(float v, __nv_bfloat16& hi, __nv_bfloat16& lo) {
    hi = __float2bfloat16(v);
    lo = __float2bfloat16(v - __bfloat162float(hi));
}
__device__ __forceinline__ uint32_t smem_u32(const void* p) {
    uint32_t a;
    asm("{ .reg .u64 t; cvta.to.shared.u64 t, %1; cvt.u32.u64 %0, t; }" : "=r"(a) : "l"(p));
    return a;
}

// ---------------- cp.async ----------------
__device__ __forceinline__ void cp16(uint32_t dst, const void* src) {
    asm volatile("cp.async.cg.shared.global [%0], [%1], 16;" :: "r"(dst), "l"(src) : "memory");
}
__device__ __forceinline__ void cp_commit() { asm volatile("cp.async.commit_group;" ::: "memory"); }
__device__ __forceinline__ void cp_wait2()  { asm volatile("cp.async.wait_group 2;" ::: "memory"); }
__device__ __forceinline__ void cp_wait0()  { asm volatile("cp.async.wait_group 0;" ::: "memory"); }

// ---------------- mma / ldmatrix ----------------
__device__ __forceinline__ void ldm_x4(uint32_t* r, uint32_t addr) {
    asm volatile("ldmatrix.sync.aligned.m8n8.x4.shared.b16 {%0,%1,%2,%3}, [%4];"
                 : "=r"(r[0]), "=r"(r[1]), "=r"(r[2]), "=r"(r[3]) : "r"(addr));
}
__device__ __forceinline__ void ldm_x2(uint32_t* r, uint32_t addr) {
    asm volatile("ldmatrix.sync.aligned.m8n8.x2.shared.b16 {%0,%1}, [%2];"
                 : "=r"(r[0]), "=r"(r[1]) : "r"(addr));
}
__device__ __forceinline__ void mma16816(float* c, const uint32_t* a, const uint32_t* b) {
    asm volatile("mma.sync.aligned.m16n8k16.row.col.f32.bf16.bf16.f32 "
                 "{%0,%1,%2,%3},{%4,%5,%6,%7},{%8,%9},{%0,%1,%2,%3};"
                 : "+f"(c[0]), "+f"(c[1]), "+f"(c[2]), "+f"(c[3])
                 : "r"(a[0]), "r"(a[1]), "r"(a[2]), "r"(a[3]), "r"(b[0]), "r"(b[1]));
}

// ---------------- bf16x3 GEMM via mma.sync ----------------
// C[M,N] = A[M,K] @ W[Npad,K]^T, A = Ah+Al, W = Bh+Bl (drop lo*lo)
// EPI: 0 = fp32 store, 1 = +res, 2 = +bias,GELU -> split bf16, 3 = +bias +res
#define TILEB  8192u            // one 128x32 bf16 tile
#define STAGEB 32768u           // Ah,Al,Bh,Bl
#define NSTAGE 4

template <int EPI>
__global__ __launch_bounds__(256, 1)
void gemm_mma(const __nv_bfloat16* __restrict__ Ah, const __nv_bfloat16* __restrict__ Al,
              const __nv_bfloat16* __restrict__ Bh, const __nv_bfloat16* __restrict__ Bl,
              const float* __restrict__ bias, const float* __restrict__ res,
              float* __restrict__ C,
              __nv_bfloat16* __restrict__ Chi, __nv_bfloat16* __restrict__ Clo,
              int N, int K)
{
    extern __shared__ char smem_raw[];
    const uint32_t sbase = smem_u32(smem_raw);

    const int tid = threadIdx.x;
    const int wid = tid >> 5;
    const int lane = tid & 31;
    const int m0 = blockIdx.y * 128;
    const int n0 = blockIdx.x * 128;
    const int wm = (wid & 1) * 64;
    const int wn = (wid >> 1) * 32;

    // ---- loader mapping: thread -> (row, chunk-pair) ----
    const int lrow = tid >> 1;          // 0..127
    const int lcp  = (tid & 1) * 2;     // chunk base 0 or 2
    const int swz  = (lrow >> 1) & 3;

    const int nch = K >> 5;             // K/32 chunks

    auto load_chunk = [&](int ci, int st) {
        const uint32_t sb = sbase + (uint32_t)st * STAGEB;
        const int k0 = ci * 32;
        const __nv_bfloat16* pAh = Ah + (size_t)(m0 + lrow) * K + k0;
        const __nv_bfloat16* pAl = Al + (size_t)(m0 + lrow) * K + k0;
        const __nv_bfloat16* pBh = Bh + (size_t)(n0 + lrow) * K + k0;
        const __nv_bfloat16* pBl = Bl + (size_t)(n0 + lrow) * K + k0;
#pragma unroll
        for (int j = 0; j < 2; j++) {
            const int ch = lcp + j;
            const uint32_t off = (uint32_t)lrow * 64u + (uint32_t)((ch ^ swz) << 4);
            cp16(sb + 0 * TILEB + off, pAh + ch * 8);
            cp16(sb + 1 * TILEB + off, pAl + ch * 8);
            cp16(sb + 2 * TILEB + off, pBh + ch * 8);
            cp16(sb + 3 * TILEB + off, pBl + ch * 8);
        }
        cp_commit();
    };

    float acc[4][4][4];
#pragma unroll
    for (int i = 0; i < 4; i++)
#pragma unroll
        for (int j = 0; j < 4; j++)
#pragma unroll
            for (int q = 0; q < 4; q++) acc[i][j][q] = 0.f;

    // prologue: stages 0..2
    load_chunk(0, 0);
    if (nch > 1) load_chunk(1, 1); else cp_commit();
    if (nch > 2) load_chunk(2, 2); else cp_commit();

    const int grp = lane >> 3;          // 0..3
    const int glr = lane & 7;

    for (int i = 0; i < nch; i++) {
        cp_wait2();
        __syncthreads();

        // issue prefetch for i+3 (stage (i+3)&3) — safe: all reads of that stage done
        if (i + 3 < nch) load_chunk(i + 3, (i + 3) & 3);
        else cp_commit();               // keep group count uniform

        const uint32_t sb = sbase + (uint32_t)(i & 3) * STAGEB;
        const uint32_t Abh = sb, Abl = sb + TILEB, Bbh = sb + 2 * TILEB, Bbl = sb + 3 * TILEB;

#pragma unroll
        for (int kk = 0; kk < 2; kk++) {
            uint32_t ah[4][4], al[4][4], bh[4][2], bl[4][2];
            const int achunk = 2 * kk + (grp >> 1);
            const int arow_b = wm + (grp & 1) * 8 + glr;
#pragma unroll
            for (int mt = 0; mt < 4; mt++) {
                const int r = arow_b + mt * 16;
                const uint32_t off = (uint32_t)r * 64u + (uint32_t)((achunk ^ ((r >> 1) & 3)) << 4);
                ldm_x4(ah[mt], Abh + off);
                ldm_x4(al[mt], Abl + off);
            }
            const int bchunk = 2 * kk + (grp & 1);
            const int brow_b = wn + glr;
#pragma unroll
            for (int nt = 0; nt < 4; nt++) {
                const int r = brow_b + nt * 8;
                const uint32_t off = (uint32_t)r * 64u + (uint32_t)((bchunk ^ ((r >> 1) & 3)) << 4);
                ldm_x2(bh[nt], Bbh + off);
                ldm_x2(bl[nt], Bbl + off);
            }
#pragma unroll
            for (int mt = 0; mt < 4; mt++)
#pragma unroll
                for (int nt = 0; nt < 4; nt++) {
                    mma16816(acc[mt][nt], ah[mt], bh[nt]);
                    mma16816(acc[mt][nt], ah[mt], bl[nt]);
                    mma16816(acc[mt][nt], al[mt], bh[nt]);
                }
        }
        __syncthreads();
    }
    cp_wait0();

    // ---- epilogue: fragment registers -> global ----
    const int rq = lane >> 2;           // 0..7
    const int cq = (lane & 3) << 1;     // 0,2,4,6
#pragma unroll
    for (int mt = 0; mt < 4; mt++) {
        const int row0 = m0 + wm + mt * 16 + rq;
        const int row1 = row0 + 8;
#pragma unroll
        for (int nt = 0; nt < 4; nt++) {
            const int col = n0 + wn + nt * 8 + cq;
            if (col >= N) continue;
            float v0 = acc[mt][nt][0], v1 = acc[mt][nt][1];
            float v2 = acc[mt][nt][2], v3 = acc[mt][nt][3];
            if (EPI == 2 || EPI == 3) {
                const float b0 = bias[col], b1 = bias[col + 1];
                v0 += b0; v1 += b1; v2 += b0; v3 += b1;
            }
            if (EPI == 2) {
                v0 = gelu_exact(v0); v1 = gelu_exact(v1);
                v2 = gelu_exact(v2); v3 = gelu_exact(v3);
            }
            if (EPI == 1 || EPI == 3) {
                const float2 r0 = *(const float2*)(res + (size_t)row0 * N + col);
                const float2 r1 = *(const float2*)(res + (size_t)row1 * N + col);
                v0 += r0.x; v1 += r0.y; v2 += r1.x; v3 += r1.y;
            }
            if (EPI == 2) {
                __nv_bfloat16 h0, l0, h1, l1, h2, l2, h3, l3;
                split_bf(v0, h0, l0); split_bf(v1, h1, l1);
                split_bf(v2, h2, l2); split_bf(v3, h3, l3);
                *(__nv_bfloat162*)(Chi + (size_t)row0 * N + col) = __nv_bfloat162(h0, h1);
                *(__nv_bfloat162*)(Chi + (size_t)row1 * N + col) = __nv_bfloat162(h2, h3);
                *(__nv_bfloat162*)(Clo + (size_t)row0 * N + col) = __nv_bfloat162(l0, l1);
                *(__nv_bfloat162*)(Clo + (size_t)row1 * N + col) = __nv_bfloat162(l2, l3);
            } else {
                *(float2*)(C + (size_t)row0 * N + col) = make_float2(v0, v1);
                *(float2*)(C + (size_t)row1 * N + col) = make_float2(v2, v3);
            }
        }
    }
}

// ---------------- weight fp32 -> bf16 hi/lo (rows beyond Nsrc zero-padded) ------
__global__ void wconv_kernel(const float* __restrict__ src,
                             __nv_bfloat16* __restrict__ hi, __nv_bfloat16* __restrict__ lo,
                             int nsrc_elems, int total)
{
    int i = blockIdx.x * blockDim.x + threadIdx.x;
    if (i >= total) return;
    float v = (i < nsrc_elems) ? src[i] : 0.0f;
    __nv_bfloat16 h, l; split_bf(v, h, l);
    hi[i] = h; lo[i] = l;
}

// ---------------- rmsnorm over 512 -> split bf16 (or fp32 out) ----------------
template <bool SPLIT>
__global__ void rmsnorm512_kernel(const float* __restrict__ x, const float* __restrict__ w,
                                  float* __restrict__ out,
                                  __nv_bfloat16* __restrict__ ohi, __nv_bfloat16* __restrict__ olo)
{
    const int row = blockIdx.x;
    const int t = threadIdx.x;                 // 128
    float4 v = ((const float4*)(x + (size_t)row * DM))[t];
    float ss = v.x * v.x + v.y * v.y + v.z * v.z + v.w * v.w;
#pragma unroll
    for (int o = 16; o; o >>= 1) ss += __shfl_xor_sync(0xffffffffu, ss, o);
    __shared__ float s[4];
    if ((t & 31) == 0) s[t >> 5] = ss;
    __syncthreads();
    float sc = rsqrtf((s[0] + s[1] + s[2] + s[3]) / (float)DM + EPSF);
    float4 wv = ((const float4*)w)[t];
    float o0 = v.x * sc * wv.x, o1 = v.y * sc * wv.y;
    float o2 = v.z * sc * wv.z, o3 = v.w * sc * wv.w;
    if (SPLIT) {
        size_t base = (size_t)row * DM + t * 4;
        __nv_bfloat16 h, l;
        split_bf(o0, h, l); ohi[base + 0] = h; olo[base + 0] = l;
        split_bf(o1, h, l); ohi[base + 1] = h; olo[base + 1] = l;
        split_bf(o2, h, l); ohi[base + 2] = h; olo[base + 2] = l;
        split_bf(o3, h, l); ohi[base + 3] = h; olo[base + 3] = l;
    } else {
        ((float4*)(out + (size_t)row * DM))[t] = make_float4(o0, o1, o2, o3);
    }
}

// ------- gated norm: yg = rmsnorm(y * silu(z), gw) -> split bf16 --------
__global__ void gatednorm_kernel(const float* __restrict__ y, const float* __restrict__ zx,
                                 const float* __restrict__ gw,
                                 __nv_bfloat16* __restrict__ ohi, __nv_bfloat16* __restrict__ olo)
{
    const int row = blockIdx.x;
    const int t = threadIdx.x;                 // 256
    float4 yv = ((const float4*)(y  + (size_t)row * DI))[t];
    float4 zv = ((const float4*)(zx + (size_t)row * DPROJ))[t];
    float4 v;
    v.x = yv.x * silu_f(zv.x); v.y = yv.y * silu_f(zv.y);
    v.z = yv.z * silu_f(zv.z); v.w = yv.w * silu_f(zv.w);
    float ss = v.x * v.x + v.y * v.y + v.z * v.z + v.w * v.w;
#pragma unroll
    for (int o = 16; o; o >>= 1) ss += __shfl_xor_sync(0xffffffffu, ss, o);
    __shared__ float s[8];
    if ((t & 31) == 0) s[t >> 5] = ss;
    __syncthreads();
    float tot = 0.f;
#pragma unroll
    for (int i = 0; i < 8; i++) tot += s[i];
    float sc = rsqrtf(tot / (float)DI + EPSF);
    float4 wv = ((const float4*)gw)[t];
    size_t base = (size_t)row * DI + t * 4;
    __nv_bfloat16 h, l;
    split_bf(v.x * sc * wv.x, h, l); ohi[base + 0] = h; olo[base + 0] = l;
    split_bf(v.y * sc * wv.y, h, l); ohi[base + 1] = h; olo[base + 1] = l;
    split_bf(v.z * sc * wv.z, h, l); ohi[base + 2] = h; olo[base + 2] = l;
    split_bf(v.w * sc * wv.w, h, l); ohi[base + 3] = h; olo[base + 3] = l;
}

// ------- causal depthwise conv (DCONV=4) + bias + SiLU -------
__global__ void conv_silu_kernel(const float* __restrict__ zx, const float* __restrict__ cw,
                                 const float* __restrict__ cb, float* __restrict__ xbc)
{
    const int c = blockIdx.x * blockDim.x + threadIdx.x;
    if (c >= CONV_DIM) return;
    const int row = blockIdx.y;
    const int l = row & (Ls - 1);
    const float* base = zx + (size_t)row * DPROJ + DI + c;
    float w0 = cw[c * 4 + 0], w1 = cw[c * 4 + 1];
    float w2 = cw[c * 4 + 2], w3 = cw[c * 4 + 3];
    float acc = cb[c];
    if (l >= 3) acc = fmaf(base[-3 * DPROJ], w0, acc);
    if (l >= 2) acc = fmaf(base[-2 * DPROJ], w1, acc);
    if (l >= 1) acc = fmaf(base[-1 * DPROJ], w2, acc);
    acc = fmaf(base[0], w3, acc);
    xbc[(size_t)row * CONV_DIM + c] = silu_f(acc);
}

// ------- dt = softplus(raw + dtb);  dA = exp(-exp(Alog) * dt) -------
__global__ void dtdA_kernel(const float* __restrict__ zx, const float* __restrict__ dtb,
                            const float* __restrict__ Alog,
                            float* __restrict__ dt, float* __restrict__ dA)
{
    const int i = blockIdx.x * blockDim.x + threadIdx.x;
    if (i >= RWS * NH) return;
    const int h = i & (NH - 1);
    const int row = i >> 4;
    float v = zx[(size_t)row * DPROJ + (DPROJ - NH) + h] + dtb[h];
    float sp = (v > 20.f) ? v : log1pf(expf(v));
    dt[i] = sp;
    dA[i] = expf(-expf(Alog[h]) * sp);
}

// ------- sequential SSM scan -------
#define SCH 64
__global__ __launch_bounds__(64)
void scan_kernel(const float* __restrict__ xbc, const float* __restrict__ dtp,
                 const float* __restrict__ dAp, const float* __restrict__ Dh,
                 float* __restrict__ y)
{
    const int h = blockIdx.x;
    const int b = blockIdx.y;
    const int p = threadIdx.x;

    __shared__ float Bs[SCH][NS], Cs[SCH][NS], xs[SCH][HD], dAs[SCH], dts[SCH];

    float st[NS];
#pragma unroll
    for (int n = 0; n < NS; n++) st[n] = 0.f;
    const float Dv = Dh[h];
    const size_t rowbase = (size_t)b * Ls;

    for (int c0 = 0; c0 < Ls; c0 += SCH) {
        for (int i = p; i < SCH * NS; i += 64) {
            int li = i >> 4, n = i & (NS - 1);
            size_t rr = rowbase + c0 + li;
            Bs[li][n] = xbc[rr * CONV_DIM + DI + n];
            Cs[li][n] = xbc[rr * CONV_DIM + DI + NS + n];
        }
        for (int li = 0; li < SCH; li++) {
            size_t rr = rowbase + c0 + li;
            xs[li][p] = xbc[rr * CONV_DIM + h * HD + p];
        }
        for (int i = p; i < SCH; i += 64) {
            size_t rr = rowbase + c0 + i;
            dts[i] = dtp[rr * NH + h];
            dAs[i] = dAp[rr * NH + h];
        }
        __syncthreads();

        for (int li = 0; li < SCH; li++) {
            const float xv = xs[li][p];
            const float coeff = dts[li] * xv;
            const float dAv = dAs[li];
            float acc = 0.f;
#pragma unroll
            for (int n = 0; n < NS; n++) {
                st[n] = fmaf(st[n], dAv, coeff * Bs[li][n]);
                acc = fmaf(st[n], Cs[li][n], acc);
            }
            size_t rr = rowbase + c0 + li;
            y[rr * DI + h * HD + p] = acc + Dv * xv;
        }
        __syncthreads();
    }
}

// ---------------- host orchestration ----------------
extern "C" void kernel_launch(void* const* d_in, const int* in_sizes, int n_in,
                              void* d_out, int out_size)
{
    const float* x_in        = (const float*)d_in[0];
    const float* in_proj_w   = (const float*)d_in[1];
    const float* conv_w      = (const float*)d_in[2];
    const float* conv_b      = (const float*)d_in[3];
    const float* dt_bias     = (const float*)d_in[4];
    const float* A_log       = (const float*)d_in[5];
    const float* D_ssm       = (const float*)d_in[6];
    const float* gnorm_w     = (const float*)d_in[7];
    const float* out_proj_w  = (const float*)d_in[8];
    const float* ffn_w1      = (const float*)d_in[9];
    const float* ffn_b1      = (const float*)d_in[10];
    const float* ffn_w2      = (const float*)d_in[11];
    const float* ffn_b2      = (const float*)d_in[12];
    const float* norm_mamba_w= (const float*)d_in[13];
    const float* norm_ffn_w  = (const float*)d_in[14];
    const float* final_norm_w= (const float*)d_in[15];
    float* out = (float*)d_out;

    float *x, *zx, *xbc, *dt, *dA, *y;
    __nv_bfloat16 *xnh, *xnl, *ygh, *ygl, *fh, *fl, *wh, *wl;
    cudaGetSymbolAddress((void**)&x,   g_x);
    cudaGetSymbolAddress((void**)&zx,  g_zx);
    cudaGetSymbolAddress((void**)&xbc, g_xbc);
    cudaGetSymbolAddress((void**)&dt,  g_dt);
    cudaGetSymbolAddress((void**)&dA,  g_dA);
    cudaGetSymbolAddress((void**)&y,   g_y);
    cudaGetSymbolAddress((void**)&xnh, g_xnh);
    cudaGetSymbolAddress((void**)&xnl, g_xnl);
    cudaGetSymbolAddress((void**)&ygh, g_ygh);
    cudaGetSymbolAddress((void**)&ygl, g_ygl);
    cudaGetSymbolAddress((void**)&fh,  g_fh);
    cudaGetSymbolAddress((void**)&fl,  g_fl);
    cudaGetSymbolAddress((void**)&wh,  g_wh);
    cudaGetSymbolAddress((void**)&wl,  g_wl);

    const int DSM = NSTAGE * (int)STAGEB;   // 131072
    cudaFuncSetAttribute(gemm_mma<0>, cudaFuncAttributeMaxDynamicSharedMemorySize, DSM);
    cudaFuncSetAttribute(gemm_mma<1>, cudaFuncAttributeMaxDynamicSharedMemorySize, DSM);
    cudaFuncSetAttribute(gemm_mma<2>, cudaFuncAttributeMaxDynamicSharedMemorySize, DSM);
    cudaFuncSetAttribute(gemm_mma<3>, cudaFuncAttributeMaxDynamicSharedMemorySize, DSM);

    cudaMemcpyAsync(x, x_in, (size_t)RWS * DM * sizeof(float), cudaMemcpyDeviceToDevice);

    // ---- weight conversion (all layers) ----
    for (int layer = 0; layer < NLAYERS; layer++) {
        size_t base = (size_t)layer * LW_TOT;
        const float* Wp = in_proj_w  + (size_t)layer * DPROJ * DM;
        const float* Wo = out_proj_w + (size_t)layer * DM * DI;
        const float* W1 = ffn_w1     + (size_t)layer * DFF * DM;
        const float* W2 = ffn_w2     + (size_t)layer * DM * DFF;
        wconv_kernel<<<(LW_IN  + 255) / 256, 256>>>(Wp, wh + base, wl + base, DPROJ * DM, LW_IN);
        wconv_kernel<<<(LW_OUT + 255) / 256, 256>>>(Wo, wh + base + LW_IN, wl + base + LW_IN, LW_OUT, LW_OUT);
        wconv_kernel<<<(LW_F1  + 255) / 256, 256>>>(W1, wh + base + LW_IN + LW_OUT, wl + base + LW_IN + LW_OUT, LW_F1, LW_F1);
        wconv_kernel<<<(LW_F2  + 255) / 256, 256>>>(W2, wh + base + LW_IN + LW_OUT + LW_F1, wl + base + LW_IN + LW_OUT + LW_F1, LW_F2, LW_F2);
    }

    for (int layer = 0; layer < NLAYERS; layer++) {
        size_t base = (size_t)layer * LW_TOT;
        const __nv_bfloat16* wih = wh + base,                          *wil = wl + base;
        const __nv_bfloat16* woh = wh + base + LW_IN,                  *wol = wl + base + LW_IN;
        const __nv_bfloat16* w1h = wh + base + LW_IN + LW_OUT,         *w1l = wl + base + LW_IN + LW_OUT;
        const __nv_bfloat16* w2h = wh + base + LW_IN + LW_OUT + LW_F1, *w2l = wl + base + LW_IN + LW_OUT + LW_F1;
        const float* cw  = conv_w  + (size_t)layer * CONV_DIM * 4;
        const float* cb  = conv_b  + (size_t)layer * CONV_DIM;
        const float* dtb = dt_bias + (size_t)layer * NH;
        const float* Al  = A_log   + (size_t)layer * NH;
        const float* Dh  = D_ssm   + (size_t)layer * NH;
        const float* gw  = gnorm_w + (size_t)layer * DI;
        const float* b1  = ffn_b1  + (size_t)layer * DFF;
        const float* b2  = ffn_b2  + (size_t)layer * DM;
        const float* nmw = norm_mamba_w + (size_t)layer * DM;
        const float* nfw = norm_ffn_w   + (size_t)layer * DM;

        // ---- Mamba block ----
        rmsnorm512_kernel<true><<<RWS, 128>>>(x, nmw, nullptr, xnh, xnl);
        gemm_mma<0><<<dim3(DPROJ_PAD / 128, RWS / 128), 256, DSM>>>(
            xnh, xnl, wih, wil, nullptr, nullptr, zx, nullptr, nullptr, DPROJ, DM);
        conv_silu_kernel<<<dim3((CONV_DIM + 255) / 256, RWS), 256>>>(zx, cw, cb, xbc);
        dtdA_kernel<<<(RWS * NH + 255) / 256, 256>>>(zx, dtb, Al, dt, dA);
        scan_kernel<<<dim3(NH, Bb), 64>>>(xbc, dt, dA, Dh, y);
        gatednorm_kernel<<<RWS, 256>>>(y, zx, gw, ygh, ygl);
        gemm_mma<1><<<dim3(DM / 128, RWS / 128), 256, DSM>>>(
            ygh, ygl, woh, wol, nullptr, x, x, nullptr, nullptr, DM, DI);

        // ---- FFN block ----
        rmsnorm512_kernel<true><<<RWS, 128>>>(x, nfw, nullptr, xnh, xnl);
        gemm_mma<2><<<dim3(DFF / 128, RWS / 128), 256, DSM>>>(
            xnh, xnl, w1h, w1l, b1, nullptr, nullptr, fh, fl, DFF, DM);
        gemm_mma<3><<<dim3(DM / 128, RWS / 128), 256, DSM>>>(
            fh, fl, w2h, w2l, b2, x, x, nullptr, nullptr, DM, DFF);
    }

    rmsnorm512_kernel<false><<<RWS, 128>>>(x, final_norm_w, out, nullptr, nullptr);
}

// round 6
// speedup vs baseline: 1.0700x; 1.0700x over previous
#include <cuda_runtime.h>
#include <cuda_bf16.h>
#include <math.h>
#include <stdint.h>

// ---------------- problem constants ----------------
#define NLAYERS 6
#define Bb      4
#define Ls      1024
#define DM      512
#define DI      1024
#define NH      16
#define HD      64
#define NS      16
#define CONV_DIM 1056
#define DPROJ   2096
#define DPROJ_PAD 2176          // 17 * 128
#define DFF     2048
#define RWS     4096            // B*L rows
#define EPSF    1e-5f

// per-layer packed weight offsets (padded, elements)
#define LW_IN   (DPROJ_PAD * DM)
#define LW_OUT  (DM * DI)
#define LW_F1   (DFF * DM)
#define LW_F2   (DM * DFF)
#define LW_TOT  (LW_IN + LW_OUT + LW_F1 + LW_F2)

// ---------------- scratch (device globals) ----------------
__device__ float g_x  [RWS * DM];
__device__ float g_zx [RWS * DPROJ];
__device__ float g_xbc[RWS * CONV_DIM];
__device__ float g_dt [RWS * NH];
__device__ float g_dA [RWS * NH];
__device__ float g_y  [RWS * DI];
__device__ __nv_bfloat16 g_xnh[RWS * DM],  g_xnl[RWS * DM];
__device__ __nv_bfloat16 g_ygh[RWS * DI],  g_ygl[RWS * DI];
__device__ __nv_bfloat16 g_fh [RWS * DFF], g_fl [RWS * DFF];
__device__ __nv_bfloat16 g_wh [NLAYERS * LW_TOT], g_wl[NLAYERS * LW_TOT];

// ---------------- small helpers ----------------
__device__ __forceinline__ float gelu_exact(float v) {
    return 0.5f * v * (1.0f + erff(v * 0.70710678118654752f));
}
__device__ __forceinline__ float silu_f(float v) {
    return v / (1.0f + expf(-v));
}
__device__ __forceinline__ void split_bf(float v, __nv_bfloat16& hi, __nv_bfloat16& lo) {
    hi = __float2bfloat16(v);
    lo = __float2bfloat16(v - __bfloat162float(hi));
}
__device__ __forceinline__ uint32_t smem_u32(const void* p) {
    uint32_t a;
    asm("{ .reg .u64 t; cvta.to.shared.u64 t, %1; cvt.u32.u64 %0, t; }" : "=r"(a) : "l"(p));
    return a;
}

// ---------------- cp.async ----------------
__device__ __forceinline__ void cp16(uint32_t dst, const void* src) {
    asm volatile("cp.async.cg.shared.global [%0], [%1], 16;" :: "r"(dst), "l"(src) : "memory");
}
__device__ __forceinline__ void cp_commit() { asm volatile("cp.async.commit_group;" ::: "memory"); }
__device__ __forceinline__ void cp_wait1()  { asm volatile("cp.async.wait_group 1;" ::: "memory"); }
__device__ __forceinline__ void cp_wait0()  { asm volatile("cp.async.wait_group 0;" ::: "memory"); }

// ---------------- mma / ldmatrix ----------------
__device__ __forceinline__ void ldm_x4(uint32_t* r, uint32_t addr) {
    asm volatile("ldmatrix.sync.aligned.m8n8.x4.shared.b16 {%0,%1,%2,%3}, [%4];"
                 : "=r"(r[0]), "=r"(r[1]), "=r"(r[2]), "=r"(r[3]) : "r"(addr));
}
__device__ __forceinline__ void ldm_x2(uint32_t* r, uint32_t addr) {
    asm volatile("ldmatrix.sync.aligned.m8n8.x2.shared.b16 {%0,%1}, [%2];"
                 : "=r"(r[0]), "=r"(r[1]) : "r"(addr));
}
__device__ __forceinline__ void mma16816(float* c, const uint32_t* a, const uint32_t* b) {
    asm volatile("mma.sync.aligned.m16n8k16.row.col.f32.bf16.bf16.f32 "
                 "{%0,%1,%2,%3},{%4,%5,%6,%7},{%8,%9},{%0,%1,%2,%3};"
                 : "+f"(c[0]), "+f"(c[1]), "+f"(c[2]), "+f"(c[3])
                 : "r"(a[0]), "r"(a[1]), "r"(a[2]), "r"(a[3]), "r"(b[0]), "r"(b[1]));
}

// ---------------- bf16x3 GEMM via mma.sync, K-chunk 64, double-buffered frags ----
// C[M,N] = A[M,K] @ W[Npad,K]^T, A = Ah+Al, W = Bh+Bl (drop lo*lo)
// EPI: 0 = fp32 store, 1 = +res, 2 = +bias,GELU -> split bf16, 3 = +bias +res
#define TILEB  16384u           // one 128x64 bf16 tile (128B rows)
#define STAGEB 65536u           // Ah,Al,Bh,Bl
#define NSTAGE 2

template <int EPI>
__global__ __launch_bounds__(256, 1)
void gemm_mma(const __nv_bfloat16* __restrict__ Ah, const __nv_bfloat16* __restrict__ Al,
              const __nv_bfloat16* __restrict__ Bh, const __nv_bfloat16* __restrict__ Bl,
              const float* __restrict__ bias, const float* __restrict__ res,
              float* __restrict__ C,
              __nv_bfloat16* __restrict__ Chi, __nv_bfloat16* __restrict__ Clo,
              int N, int K)
{
    extern __shared__ char smem_raw[];
    const uint32_t sbase = smem_u32(smem_raw);

    const int tid = threadIdx.x;
    const int wid = tid >> 5;
    const int lane = tid & 31;
    const int m0 = blockIdx.y * 128;
    const int n0 = blockIdx.x * 128;
    const int wm = (wid & 1) * 64;
    const int wn = (wid >> 1) * 32;
    const int grp = lane >> 3;          // 0..3
    const int glr = lane & 7;

    // ---- loader mapping ----
    const int lrow = tid >> 1;          // 0..127
    const int half = tid & 1;           // which 32-elem half of the 64-K row
    const int nch = K >> 6;             // K/64 chunks

    auto load_chunk = [&](int ci, int st) {
        const uint32_t sb = sbase + (uint32_t)st * STAGEB;
        const int k0 = ci * 64 + half * 32;
        const __nv_bfloat16* pAh = Ah + (size_t)(m0 + lrow) * K + k0;
        const __nv_bfloat16* pAl = Al + (size_t)(m0 + lrow) * K + k0;
        const __nv_bfloat16* pBh = Bh + (size_t)(n0 + lrow) * K + k0;
        const __nv_bfloat16* pBl = Bl + (size_t)(n0 + lrow) * K + k0;
#pragma unroll
        for (int j = 0; j < 4; j++) {
            const int ch = half * 4 + j;
            const uint32_t off = (uint32_t)lrow * 128u + (uint32_t)((ch ^ (lrow & 7)) << 4);
            cp16(sb + 0 * TILEB + off, pAh + j * 8);
            cp16(sb + 1 * TILEB + off, pAl + j * 8);
            cp16(sb + 2 * TILEB + off, pBh + j * 8);
            cp16(sb + 3 * TILEB + off, pBl + j * 8);
        }
        cp_commit();
    };

    float acc[4][4][4];
#pragma unroll
    for (int i = 0; i < 4; i++)
#pragma unroll
        for (int j = 0; j < 4; j++)
#pragma unroll
            for (int q = 0; q < 4; q++) acc[i][j][q] = 0.f;

    uint32_t ah0[4][4], al0[4][4], bh0[4][2], bl0[4][2];
    uint32_t ah1[4][4], al1[4][4], bh1[4][2], bl1[4][2];

    auto ldfrags = [&](uint32_t sb, int kk,
                       uint32_t (*ah)[4], uint32_t (*al)[4],
                       uint32_t (*bh)[2], uint32_t (*bl)[2]) {
        const uint32_t Abh = sb, Abl = sb + TILEB, Bbh = sb + 2 * TILEB, Bbl = sb + 3 * TILEB;
        const int achunk = 2 * kk + (grp >> 1);
        const int arow_b = wm + (grp & 1) * 8 + glr;
#pragma unroll
        for (int mt = 0; mt < 4; mt++) {
            const int r = arow_b + mt * 16;
            const uint32_t off = (uint32_t)r * 128u + (uint32_t)((achunk ^ (r & 7)) << 4);
            ldm_x4(ah[mt], Abh + off);
            ldm_x4(al[mt], Abl + off);
        }
        const int bchunk = 2 * kk + (grp & 1);
        const int brow_b = wn + glr;
#pragma unroll
        for (int nt = 0; nt < 4; nt++) {
            const int r = brow_b + nt * 8;
            const uint32_t off = (uint32_t)r * 128u + (uint32_t)((bchunk ^ (r & 7)) << 4);
            ldm_x2(bh[nt], Bbh + off);
            ldm_x2(bl[nt], Bbl + off);
        }
    };

    auto do_mma = [&](uint32_t (*ah)[4], uint32_t (*al)[4],
                      uint32_t (*bh)[2], uint32_t (*bl)[2]) {
#pragma unroll
        for (int mt = 0; mt < 4; mt++)
#pragma unroll
            for (int nt = 0; nt < 4; nt++) {
                mma16816(acc[mt][nt], ah[mt], bh[nt]);
                mma16816(acc[mt][nt], ah[mt], bl[nt]);
                mma16816(acc[mt][nt], al[mt], bh[nt]);
            }
    };

    // prologue
    load_chunk(0, 0);
    if (nch > 1) load_chunk(1, 1); else cp_commit();
    cp_wait1();
    __syncthreads();
    ldfrags(sbase, 0, ah0, al0, bh0, bl0);

    for (int i = 0; i < nch; i++) {
        const uint32_t sb  = sbase + (uint32_t)(i & 1) * STAGEB;
        const uint32_t sbn = sbase + (uint32_t)((i + 1) & 1) * STAGEB;

        ldfrags(sb, 1, ah1, al1, bh1, bl1);
        do_mma(ah0, al0, bh0, bl0);                    // kk0
        ldfrags(sb, 2, ah0, al0, bh0, bl0);
        do_mma(ah1, al1, bh1, bl1);                    // kk1
        ldfrags(sb, 3, ah1, al1, bh1, bl1);
        do_mma(ah0, al0, bh0, bl0);                    // kk2

        cp_wait0();                                     // stage i+1 complete
        __syncthreads();                                // all warps done reading stage i
        if (i + 2 < nch) load_chunk(i + 2, i & 1); else cp_commit();
        ldfrags(sbn, 0, ah0, al0, bh0, bl0);            // next stage kk0 (garbage on last iter, unused)
        do_mma(ah1, al1, bh1, bl1);                    // kk3
    }

    // ---- epilogue: fragment registers -> global ----
    const int rq = lane >> 2;           // 0..7
    const int cq = (lane & 3) << 1;     // 0,2,4,6
#pragma unroll
    for (int mt = 0; mt < 4; mt++) {
        const int row0 = m0 + wm + mt * 16 + rq;
        const int row1 = row0 + 8;
#pragma unroll
        for (int nt = 0; nt < 4; nt++) {
            const int col = n0 + wn + nt * 8 + cq;
            if (col >= N) continue;
            float v0 = acc[mt][nt][0], v1 = acc[mt][nt][1];
            float v2 = acc[mt][nt][2], v3 = acc[mt][nt][3];
            if (EPI == 2 || EPI == 3) {
                const float b0 = bias[col], b1 = bias[col + 1];
                v0 += b0; v1 += b1; v2 += b0; v3 += b1;
            }
            if (EPI == 2) {
                v0 = gelu_exact(v0); v1 = gelu_exact(v1);
                v2 = gelu_exact(v2); v3 = gelu_exact(v3);
            }
            if (EPI == 1 || EPI == 3) {
                const float2 r0 = *(const float2*)(res + (size_t)row0 * N + col);
                const float2 r1 = *(const float2*)(res + (size_t)row1 * N + col);
                v0 += r0.x; v1 += r0.y; v2 += r1.x; v3 += r1.y;
            }
            if (EPI == 2) {
                __nv_bfloat16 h0, l0, h1, l1, h2, l2, h3, l3;
                split_bf(v0, h0, l0); split_bf(v1, h1, l1);
                split_bf(v2, h2, l2); split_bf(v3, h3, l3);
                *(__nv_bfloat162*)(Chi + (size_t)row0 * N + col) = __nv_bfloat162(h0, h1);
                *(__nv_bfloat162*)(Chi + (size_t)row1 * N + col) = __nv_bfloat162(h2, h3);
                *(__nv_bfloat162*)(Clo + (size_t)row0 * N + col) = __nv_bfloat162(l0, l1);
                *(__nv_bfloat162*)(Clo + (size_t)row1 * N + col) = __nv_bfloat162(l2, l3);
            } else {
                *(float2*)(C + (size_t)row0 * N + col) = make_float2(v0, v1);
                *(float2*)(C + (size_t)row1 * N + col) = make_float2(v2, v3);
            }
        }
    }
}

// ---------------- weight fp32 -> bf16 hi/lo, vectorized x4 ----------------
__global__ void wconv4_kernel(const float4* __restrict__ src,
                              __nv_bfloat162* __restrict__ hi, __nv_bfloat162* __restrict__ lo,
                              int nsrc4, int total4)
{
    int i = blockIdx.x * blockDim.x + threadIdx.x;
    if (i >= total4) return;
    float4 v = (i < nsrc4) ? src[i] : make_float4(0.f, 0.f, 0.f, 0.f);
    __nv_bfloat16 h0, l0, h1, l1, h2, l2, h3, l3;
    split_bf(v.x, h0, l0); split_bf(v.y, h1, l1);
    split_bf(v.z, h2, l2); split_bf(v.w, h3, l3);
    hi[2 * i + 0] = __nv_bfloat162(h0, h1);
    hi[2 * i + 1] = __nv_bfloat162(h2, h3);
    lo[2 * i + 0] = __nv_bfloat162(l0, l1);
    lo[2 * i + 1] = __nv_bfloat162(l2, l3);
}

// ---------------- rmsnorm over 512 -> split bf16 (or fp32 out) ----------------
template <bool SPLIT>
__global__ void rmsnorm512_kernel(const float* __restrict__ x, const float* __restrict__ w,
                                  float* __restrict__ out,
                                  __nv_bfloat16* __restrict__ ohi, __nv_bfloat16* __restrict__ olo)
{
    const int row = blockIdx.x;
    const int t = threadIdx.x;                 // 128
    float4 v = ((const float4*)(x + (size_t)row * DM))[t];
    float ss = v.x * v.x + v.y * v.y + v.z * v.z + v.w * v.w;
#pragma unroll
    for (int o = 16; o; o >>= 1) ss += __shfl_xor_sync(0xffffffffu, ss, o);
    __shared__ float s[4];
    if ((t & 31) == 0) s[t >> 5] = ss;
    __syncthreads();
    float sc = rsqrtf((s[0] + s[1] + s[2] + s[3]) / (float)DM + EPSF);
    float4 wv = ((const float4*)w)[t];
    float o0 = v.x * sc * wv.x, o1 = v.y * sc * wv.y;
    float o2 = v.z * sc * wv.z, o3 = v.w * sc * wv.w;
    if (SPLIT) {
        size_t base = (size_t)row * DM + t * 4;
        __nv_bfloat16 h, l;
        split_bf(o0, h, l); ohi[base + 0] = h; olo[base + 0] = l;
        split_bf(o1, h, l); ohi[base + 1] = h; olo[base + 1] = l;
        split_bf(o2, h, l); ohi[base + 2] = h; olo[base + 2] = l;
        split_bf(o3, h, l); ohi[base + 3] = h; olo[base + 3] = l;
    } else {
        ((float4*)(out + (size_t)row * DM))[t] = make_float4(o0, o1, o2, o3);
    }
}

// ------- gated norm: yg = rmsnorm(y * silu(z), gw) -> split bf16 --------
__global__ void gatednorm_kernel(const float* __restrict__ y, const float* __restrict__ zx,
                                 const float* __restrict__ gw,
                                 __nv_bfloat16* __restrict__ ohi, __nv_bfloat16* __restrict__ olo)
{
    const int row = blockIdx.x;
    const int t = threadIdx.x;                 // 256
    float4 yv = ((const float4*)(y  + (size_t)row * DI))[t];
    float4 zv = ((const float4*)(zx + (size_t)row * DPROJ))[t];
    float4 v;
    v.x = yv.x * silu_f(zv.x); v.y = yv.y * silu_f(zv.y);
    v.z = yv.z * silu_f(zv.z); v.w = yv.w * silu_f(zv.w);
    float ss = v.x * v.x + v.y * v.y + v.z * v.z + v.w * v.w;
#pragma unroll
    for (int o = 16; o; o >>= 1) ss += __shfl_xor_sync(0xffffffffu, ss, o);
    __shared__ float s[8];
    if ((t & 31) == 0) s[t >> 5] = ss;
    __syncthreads();
    float tot = 0.f;
#pragma unroll
    for (int i = 0; i < 8; i++) tot += s[i];
    float sc = rsqrtf(tot / (float)DI + EPSF);
    float4 wv = ((const float4*)gw)[t];
    size_t base = (size_t)row * DI + t * 4;
    __nv_bfloat16 h, l;
    split_bf(v.x * sc * wv.x, h, l); ohi[base + 0] = h; olo[base + 0] = l;
    split_bf(v.y * sc * wv.y, h, l); ohi[base + 1] = h; olo[base + 1] = l;
    split_bf(v.z * sc * wv.z, h, l); ohi[base + 2] = h; olo[base + 2] = l;
    split_bf(v.w * sc * wv.w, h, l); ohi[base + 3] = h; olo[base + 3] = l;
}

// ------- causal depthwise conv (DCONV=4) + bias + SiLU -------
__global__ void conv_silu_kernel(const float* __restrict__ zx, const float* __restrict__ cw,
                                 const float* __restrict__ cb, float* __restrict__ xbc)
{
    const int c = blockIdx.x * blockDim.x + threadIdx.x;
    if (c >= CONV_DIM) return;
    const int row = blockIdx.y;
    const int l = row & (Ls - 1);
    const float* base = zx + (size_t)row * DPROJ + DI + c;
    float w0 = cw[c * 4 + 0], w1 = cw[c * 4 + 1];
    float w2 = cw[c * 4 + 2], w3 = cw[c * 4 + 3];
    float acc = cb[c];
    if (l >= 3) acc = fmaf(base[-3 * DPROJ], w0, acc);
    if (l >= 2) acc = fmaf(base[-2 * DPROJ], w1, acc);
    if (l >= 1) acc = fmaf(base[-1 * DPROJ], w2, acc);
    acc = fmaf(base[0], w3, acc);
    xbc[(size_t)row * CONV_DIM + c] = silu_f(acc);
}

// ------- dt = softplus(raw + dtb);  dA = exp(-exp(Alog) * dt) -------
__global__ void dtdA_kernel(const float* __restrict__ zx, const float* __restrict__ dtb,
                            const float* __restrict__ Alog,
                            float* __restrict__ dt, float* __restrict__ dA)
{
    const int i = blockIdx.x * blockDim.x + threadIdx.x;
    if (i >= RWS * NH) return;
    const int h = i & (NH - 1);
    const int row = i >> 4;
    float v = zx[(size_t)row * DPROJ + (DPROJ - NH) + h] + dtb[h];
    float sp = (v > 20.f) ? v : log1pf(expf(v));
    dt[i] = sp;
    dA[i] = expf(-expf(Alog[h]) * sp);
}

// ------- sequential SSM scan -------
#define SCH 64
__global__ __launch_bounds__(64)
void scan_kernel(const float* __restrict__ xbc, const float* __restrict__ dtp,
                 const float* __restrict__ dAp, const float* __restrict__ Dh,
                 float* __restrict__ y)
{
    const int h = blockIdx.x;
    const int b = blockIdx.y;
    const int p = threadIdx.x;

    __shared__ float Bs[SCH][NS], Cs[SCH][NS], xs[SCH][HD], dAs[SCH], dts[SCH];

    float st[NS];
#pragma unroll
    for (int n = 0; n < NS; n++) st[n] = 0.f;
    const float Dv = Dh[h];
    const size_t rowbase = (size_t)b * Ls;

    for (int c0 = 0; c0 < Ls; c0 += SCH) {
        for (int i = p; i < SCH * NS; i += 64) {
            int li = i >> 4, n = i & (NS - 1);
            size_t rr = rowbase + c0 + li;
            Bs[li][n] = xbc[rr * CONV_DIM + DI + n];
            Cs[li][n] = xbc[rr * CONV_DIM + DI + NS + n];
        }
        for (int li = 0; li < SCH; li++) {
            size_t rr = rowbase + c0 + li;
            xs[li][p] = xbc[rr * CONV_DIM + h * HD + p];
        }
        for (int i = p; i < SCH; i += 64) {
            size_t rr = rowbase + c0 + i;
            dts[i] = dtp[rr * NH + h];
            dAs[i] = dAp[rr * NH + h];
        }
        __syncthreads();

        for (int li = 0; li < SCH; li++) {
            const float xv = xs[li][p];
            const float coeff = dts[li] * xv;
            const float dAv = dAs[li];
            float a0 = 0.f, a1 = 0.f, a2 = 0.f, a3 = 0.f;
#pragma unroll
            for (int n = 0; n < NS; n += 4) {
                st[n + 0] = fmaf(st[n + 0], dAv, coeff * Bs[li][n + 0]);
                a0 = fmaf(st[n + 0], Cs[li][n + 0], a0);
                st[n + 1] = fmaf(st[n + 1], dAv, coeff * Bs[li][n + 1]);
                a1 = fmaf(st[n + 1], Cs[li][n + 1], a1);
                st[n + 2] = fmaf(st[n + 2], dAv, coeff * Bs[li][n + 2]);
                a2 = fmaf(st[n + 2], Cs[li][n + 2], a2);
                st[n + 3] = fmaf(st[n + 3], dAv, coeff * Bs[li][n + 3]);
                a3 = fmaf(st[n + 3], Cs[li][n + 3], a3);
            }
            size_t rr = rowbase + c0 + li;
            y[rr * DI + h * HD + p] = ((a0 + a1) + (a2 + a3)) + Dv * xv;
        }
        __syncthreads();
    }
}

// ---------------- host orchestration ----------------
extern "C" void kernel_launch(void* const* d_in, const int* in_sizes, int n_in,
                              void* d_out, int out_size)
{
    const float* x_in        = (const float*)d_in[0];
    const float* in_proj_w   = (const float*)d_in[1];
    const float* conv_w      = (const float*)d_in[2];
    const float* conv_b      = (const float*)d_in[3];
    const float* dt_bias     = (const float*)d_in[4];
    const float* A_log       = (const float*)d_in[5];
    const float* D_ssm       = (const float*)d_in[6];
    const float* gnorm_w     = (const float*)d_in[7];
    const float* out_proj_w  = (const float*)d_in[8];
    const float* ffn_w1      = (const float*)d_in[9];
    const float* ffn_b1      = (const float*)d_in[10];
    const float* ffn_w2      = (const float*)d_in[11];
    const float* ffn_b2      = (const float*)d_in[12];
    const float* norm_mamba_w= (const float*)d_in[13];
    const float* norm_ffn_w  = (const float*)d_in[14];
    const float* final_norm_w= (const float*)d_in[15];
    float* out = (float*)d_out;

    float *x, *zx, *xbc, *dt, *dA, *y;
    __nv_bfloat16 *xnh, *xnl, *ygh, *ygl, *fh, *fl, *wh, *wl;
    cudaGetSymbolAddress((void**)&x,   g_x);
    cudaGetSymbolAddress((void**)&zx,  g_zx);
    cudaGetSymbolAddress((void**)&xbc, g_xbc);
    cudaGetSymbolAddress((void**)&dt,  g_dt);
    cudaGetSymbolAddress((void**)&dA,  g_dA);
    cudaGetSymbolAddress((void**)&y,   g_y);
    cudaGetSymbolAddress((void**)&xnh, g_xnh);
    cudaGetSymbolAddress((void**)&xnl, g_xnl);
    cudaGetSymbolAddress((void**)&ygh, g_ygh);
    cudaGetSymbolAddress((void**)&ygl, g_ygl);
    cudaGetSymbolAddress((void**)&fh,  g_fh);
    cudaGetSymbolAddress((void**)&fl,  g_fl);
    cudaGetSymbolAddress((void**)&wh,  g_wh);
    cudaGetSymbolAddress((void**)&wl,  g_wl);

    const int DSM = NSTAGE * (int)STAGEB;   // 131072
    cudaFuncSetAttribute(gemm_mma<0>, cudaFuncAttributeMaxDynamicSharedMemorySize, DSM);
    cudaFuncSetAttribute(gemm_mma<1>, cudaFuncAttributeMaxDynamicSharedMemorySize, DSM);
    cudaFuncSetAttribute(gemm_mma<2>, cudaFuncAttributeMaxDynamicSharedMemorySize, DSM);
    cudaFuncSetAttribute(gemm_mma<3>, cudaFuncAttributeMaxDynamicSharedMemorySize, DSM);

    cudaMemcpyAsync(x, x_in, (size_t)RWS * DM * sizeof(float), cudaMemcpyDeviceToDevice);

    // ---- weight conversion (all layers), vectorized ----
    for (int layer = 0; layer < NLAYERS; layer++) {
        size_t base = (size_t)layer * LW_TOT;
        const float* Wp = in_proj_w  + (size_t)layer * DPROJ * DM;
        const float* Wo = out_proj_w + (size_t)layer * DM * DI;
        const float* W1 = ffn_w1     + (size_t)layer * DFF * DM;
        const float* W2 = ffn_w2     + (size_t)layer * DM * DFF;
        wconv4_kernel<<<(LW_IN / 4 + 255) / 256, 256>>>(
            (const float4*)Wp, (__nv_bfloat162*)(wh + base), (__nv_bfloat162*)(wl + base),
            DPROJ * DM / 4, LW_IN / 4);
        wconv4_kernel<<<(LW_OUT / 4 + 255) / 256, 256>>>(
            (const float4*)Wo, (__nv_bfloat162*)(wh + base + LW_IN), (__nv_bfloat162*)(wl + base + LW_IN),
            LW_OUT / 4, LW_OUT / 4);
        wconv4_kernel<<<(LW_F1 / 4 + 255) / 256, 256>>>(
            (const float4*)W1, (__nv_bfloat162*)(wh + base + LW_IN + LW_OUT),
            (__nv_bfloat162*)(wl + base + LW_IN + LW_OUT), LW_F1 / 4, LW_F1 / 4);
        wconv4_kernel<<<(LW_F2 / 4 + 255) / 256, 256>>>(
            (const float4*)W2, (__nv_bfloat162*)(wh + base + LW_IN + LW_OUT + LW_F1),
            (__nv_bfloat162*)(wl + base + LW_IN + LW_OUT + LW_F1), LW_F2 / 4, LW_F2 / 4);
    }

    for (int layer = 0; layer < NLAYERS; layer++) {
        size_t base = (size_t)layer * LW_TOT;
        const __nv_bfloat16* wih = wh + base,                          *wil = wl + base;
        const __nv_bfloat16* woh = wh + base + LW_IN,                  *wol = wl + base + LW_IN;
        const __nv_bfloat16* w1h = wh + base + LW_IN + LW_OUT,         *w1l = wl + base + LW_IN + LW_OUT;
        const __nv_bfloat16* w2h = wh + base + LW_IN + LW_OUT + LW_F1, *w2l = wl + base + LW_IN + LW_OUT + LW_F1;
        const float* cw  = conv_w  + (size_t)layer * CONV_DIM * 4;
        const float* cb  = conv_b  + (size_t)layer * CONV_DIM;
        const float* dtb = dt_bias + (size_t)layer * NH;
        const float* Al  = A_log   + (size_t)layer * NH;
        const float* Dh  = D_ssm   + (size_t)layer * NH;
        const float* gw  = gnorm_w + (size_t)layer * DI;
        const float* b1  = ffn_b1  + (size_t)layer * DFF;
        const float* b2  = ffn_b2  + (size_t)layer * DM;
        const float* nmw = norm_mamba_w + (size_t)layer * DM;
        const float* nfw = norm_ffn_w   + (size_t)layer * DM;

        // ---- Mamba block ----
        rmsnorm512_kernel<true><<<RWS, 128>>>(x, nmw, nullptr, xnh, xnl);
        gemm_mma<0><<<dim3(DPROJ_PAD / 128, RWS / 128), 256, DSM>>>(
            xnh, xnl, wih, wil, nullptr, nullptr, zx, nullptr, nullptr, DPROJ, DM);
        conv_silu_kernel<<<dim3((CONV_DIM + 255) / 256, RWS), 256>>>(zx, cw, cb, xbc);
        dtdA_kernel<<<(RWS * NH + 255) / 256, 256>>>(zx, dtb, Al, dt, dA);
        scan_kernel<<<dim3(NH, Bb), 64>>>(xbc, dt, dA, Dh, y);
        gatednorm_kernel<<<RWS, 256>>>(y, zx, gw, ygh, ygl);
        gemm_mma<1><<<dim3(DM / 128, RWS / 128), 256, DSM>>>(
            ygh, ygl, woh, wol, nullptr, x, x, nullptr, nullptr, DM, DI);

        // ---- FFN block ----
        rmsnorm512_kernel<true><<<RWS, 128>>>(x, nfw, nullptr, xnh, xnl);
        gemm_mma<2><<<dim3(DFF / 128, RWS / 128), 256, DSM>>>(
            xnh, xnl, w1h, w1l, b1, nullptr, nullptr, fh, fl, DFF, DM);
        gemm_mma<3><<<dim3(DM / 128, RWS / 128), 256, DSM>>>(
            fh, fl, w2h, w2l, b2, x, x, nullptr, nullptr, DM, DFF);
    }

    rmsnorm512_kernel<false><<<RWS, 128>>>(x, final_norm_w, out, nullptr, nullptr);
}